// round 10
// baseline (speedup 1.0000x reference)
#include <cuda_runtime.h>

// ---------------- problem constants ----------------
#define Bn 16
#define An 3
#define Cn 80
#define Hn 76
#define Wn 76
#define Tn 50
#define HW (Hn * Wn)          // 5776
#define AHW (An * HW)         // 17328
#define NCELL (Bn * AHW)      // 277248
#define NT (Bn * Tn)          // 800
#define CH (5 + Cn)           // 85
#define NCH (An * CH)         // 255
#define NREP 8
#define NBB (Bn * NREP)       // 128 batch-replica blocks
#define NBLK 148
#define NTHR 512
#define NWARP (NTHR / 32)

// ---------------- device state (static, zero-init; no allocations) ----------------
__device__ int          g_win[NREP * NCELL];  // per-replica winner tables (self-cleaned)
__device__ double       g_acc[8];             // 0:x 1:y 2:w 3:h 4:conf_obj 5:conf_all 6:conf_zero 7:cls
__device__ unsigned int g_done;               // ticket (winner-reset)
__device__ int          g_nm_tot, g_nz_tot;   // winner-reset

#define LOG2E 1.4426950408889634f
#define LN2   0.6931471805599453f

// softplus(l) = -log(1-sigmoid(l)) = log(1+e^l); clip(-100) never active for |l| < 17
__device__ __forceinline__ float spf(float l) {
    return LN2 * __log2f(1.0f + exp2f(l * LOG2E));
}
// sum of 4 softplus via one log of product (5 MUFU / 4 terms); product < 3e8 for |l|<6
__device__ __forceinline__ float sp4(float a, float b, float c, float d) {
    float p = (1.0f + exp2f(a * LOG2E)) * (1.0f + exp2f(b * LOG2E))
            * (1.0f + exp2f(c * LOG2E)) * (1.0f + exp2f(d * LOG2E));
    return LN2 * __log2f(p);
}

__global__ __launch_bounds__(NTHR, 1)
void yolo_one(const float* __restrict__ in, const float* __restrict__ tgt,
              float* __restrict__ out)
{
    __shared__ int    s_mcell[16];     // ≤7 winners per replica
    __shared__ float4 s_mt[16];
    __shared__ int    s_pl[16];        // ≤7 pairs per replica
    __shared__ int    s_zc[32];        // ≤21 z-cells per replica
    __shared__ int    s_nm, s_np, s_nz;
    __shared__ double sred[NWARP][8];

    const int tid = threadIdx.x, bid = blockIdx.x;
    double acc[8];
#pragma unroll
    for (int i = 0; i < 8; i++) acc[i] = 0.0;

    // ================= batch-replica blocks: target build + gather terms =========
    if (bid < NBB) {
        const int b = bid & (Bn - 1);          // batch
        const int r = bid >> 4;                // replica 0..7
        if (tid == 0) { s_nm = 0; s_np = 0; s_nz = 0; }
        __syncthreads();

        const int t = tid;                     // target index within batch
        const bool active = (t < Tn);
        const int j = b * Tn + t;

        // ---- R9-VERBATIM per-target math ----
        float c = 0.f, xx = 0.f, yy = 0.f, ww = 0.f, hh = 0.f;
        if (active) {
            const float* p = tgt + j * 5;
            c = p[0]; xx = p[1]; yy = p[2]; ww = p[3]; hh = p[4];
        }
        bool valid = active && ((c + xx + yy + ww + hh) != 0.0f);

        float gx = xx * (float)Wn, gy = yy * (float)Hn;
        float gw = ww * (float)Wn, gh = hh * (float)Hn;
        int gi = (int)gx, gj = (int)gy;

        const float aw0 = 1.25f,  aw1 = 2.0f,  aw2 = 4.125f;
        const float ah0 = 1.625f, ah1 = 3.75f, ah2 = 2.875f;
        const float a20 = 5.90625f, a21 = 14.25f, a22 = 19.859375f;

        float a1 = (gw + 1.0f) * (gh + 1.0f);
        float i0 = fmaxf(fminf(gw, aw0) + 1.0f, 0.0f) * fmaxf(fminf(gh, ah0) + 1.0f, 0.0f);
        float i1 = fmaxf(fminf(gw, aw1) + 1.0f, 0.0f) * fmaxf(fminf(gh, ah1) + 1.0f, 0.0f);
        float i2 = fmaxf(fminf(gw, aw2) + 1.0f, 0.0f) * fmaxf(fminf(gh, ah2) + 1.0f, 0.0f);
        float u0 = i0 / (a1 + a20 - i0 + 1e-16f);
        float u1 = i1 / (a1 + a21 - i1 + 1e-16f);
        float u2 = i2 / (a1 + a22 - i2 + 1e-16f);

        int best = 0; float bi = u0;
        if (u1 > bi) { best = 1; bi = u1; }
        if (u2 > bi) { best = 2; bi = u2; }

        bool ok = valid && (gj < Hn) && (gi < Wn) && (gj >= 0) && (gi >= 0);
        int cell = ((b * An + best) * Hn + gj) * Wn + gi;

        const bool mine = ((t & (NREP - 1)) == r);   // deterministic partition by t
        int* win = g_win + r * NCELL;                // replica-private table

        // clear-then-max election, bit-identical to R9 (block-local contest)
        if (ok) win[cell] = 0;
        __syncthreads();
        if (ok) atomicMax(&win[cell], t + 1);

        if (valid && mine) {
            if (u0 > 0.5f) { int z = ((b * An + 0) * Hn + gj) * Wn + gi;
                             if (z >= 0 && z < NCELL) s_zc[atomicAdd(&s_nz, 1)] = z; }
            if (u1 > 0.5f) { int z = ((b * An + 1) * Hn + gj) * Wn + gi;
                             if (z >= 0 && z < NCELL) s_zc[atomicAdd(&s_nz, 1)] = z; }
            if (u2 > 0.5f) { int z = ((b * An + 2) * Hn + gj) * Wn + gi;
                             if (z >= 0 && z < NCELL) s_zc[atomicAdd(&s_nz, 1)] = z; }
        }
        if (ok && mine) s_pl[atomicAdd(&s_np, 1)] = cell * Cn + (int)c;

        __syncthreads();

        if (ok && mine && win[cell] == t + 1) {
            float tx = gx - (float)gi;
            float ty = gy - (float)gj;
            float awb = (best == 0) ? aw0 : (best == 1 ? aw1 : aw2);
            float ahb = (best == 0) ? ah0 : (best == 1 ? ah1 : ah2);
            float tw = logf(gw / awb + 1e-16f);
            float th = logf(gh / ahb + 1e-16f);
            int m = atomicAdd(&s_nm, 1);
            s_mcell[m] = cell;
            s_mt[m] = make_float4(tx, ty, tw, th);
        }
        __syncthreads();

        if (tid == 0) { atomicAdd(&g_nm_tot, s_nm); atomicAdd(&g_nz_tot, s_nz); }

        // ---- block-local gather segments ----
        const int nmL = s_nm, npL = s_np, nzL = s_nz;
        const int G1 = nmL;                 // masked x/y/w/h/conf
        const int G2 = G1 + nmL * 20;       // class terms, groups of 4
        const int G3 = G2 + npL;            // pair corrections (exact -logit)
        const int G4 = G3 + nzL;            // noobj-zeroed conf terms

        for (int i = tid; i < G4; i += NTHR) {
            if (i < G1) {
                int cell2 = s_mcell[i]; float4 tv = s_mt[i];
                int bb = cell2 / AHW, rr = cell2 - bb * AHW;
                int a = rr / HW,     hw = rr - a * HW;
                const float* base = in + (size_t)(bb * NCH + a * CH) * HW + hw;
                float xl = base[0], yl = base[HW], wl = base[2 * HW];
                float hl = base[3 * HW], cl = base[4 * HW];
                acc[0] += (double)(tv.x * spf(-xl) + (1.0f - tv.x) * spf(xl));
                acc[1] += (double)(tv.y * spf(-yl) + (1.0f - tv.y) * spf(yl));
                float dw = wl - tv.z, dh = hl - tv.w;
                acc[2] += (double)(dw * dw);
                acc[3] += (double)(dh * dh);
                acc[4] += (double)spf(-cl);
            } else if (i < G2) {
                int idx = i - G1;
                int k = idx / 20, g = idx - k * 20;
                int cell2 = s_mcell[k];
                int bb = cell2 / AHW, rr = cell2 - bb * AHW;
                int a = rr / HW,     hw = rr - a * HW;
                const float* base = in + (size_t)(bb * NCH + a * CH + 5 + g * 4) * HW + hw;
                acc[7] += (double)sp4(base[0], base[HW], base[2 * HW], base[3 * HW]);
            } else if (i < G3) {
                int key = s_pl[i - G2];
                int cell2 = key / Cn, cc = key - cell2 * Cn;
                int bb = cell2 / AHW, rr = cell2 - bb * AHW;
                int a = rr / HW,     hw = rr - a * HW;
                acc[7] += (double)(-in[(size_t)(bb * NCH + a * CH + 5 + cc) * HW + hw]);
            } else {
                int cell2 = s_zc[i - G3];
                int bb = cell2 / AHW, rr = cell2 - bb * AHW;
                int a = rr / HW,     hw = rr - a * HW;
                acc[6] += (double)spf(in[(size_t)(bb * NCH + a * CH + 4) * HW + hw]);
            }
        }
    }

    // ================= conf segment over all cells (all blocks) ==================
    const int N4 = NCELL / 4;
    for (int i = bid * NTHR + tid; i < N4; i += NBLK * NTHR) {
        int c4 = i * 4;
        int bb = c4 / AHW, rr = c4 - bb * AHW;
        int a = rr / HW,   hw = rr - a * HW;
        const float4 v = *(const float4*)(in + (size_t)(bb * NCH + a * CH + 4) * HW + hw);
        acc[5] += (double)sp4(v.x, v.y, v.z, v.w);
    }

    // ================= reduction: warp -> smem -> single-thread atomics ==========
#pragma unroll
    for (int off = 16; off; off >>= 1)
#pragma unroll
        for (int i = 0; i < 8; i++)
            acc[i] += __shfl_down_sync(0xffffffffu, acc[i], off);

    int warp = tid >> 5, lane = tid & 31;
    if (lane == 0)
#pragma unroll
        for (int i = 0; i < 8; i++) sred[warp][i] = acc[i];
    __syncthreads();

    if (tid == 0) {
#pragma unroll
        for (int i = 0; i < 8; i++) {
            double s = 0.0;
            for (int w = 0; w < NWARP; w++) s += sred[w][i];
            atomicAdd(&g_acc[i], s);
        }
        __threadfence();                       // adds visible before ticket
        unsigned n = atomicAdd(&g_done, 1u);
        if (n == (unsigned)(NBLK - 1)) {
            // ---- winner: finalize (reads via L2 atomics) + reset ----
            double a0 = atomicAdd(&g_acc[0], 0.0), a1v = atomicAdd(&g_acc[1], 0.0);
            double a2v = atomicAdd(&g_acc[2], 0.0), a3 = atomicAdd(&g_acc[3], 0.0);
            double a4 = atomicAdd(&g_acc[4], 0.0), a5 = atomicAdd(&g_acc[5], 0.0);
            double a6 = atomicAdd(&g_acc[6], 0.0), a7 = atomicAdd(&g_acc[7], 0.0);
            int nmv = atomicAdd(&g_nm_tot, 0), nzv = atomicAdd(&g_nz_tot, 0);

            float nm  = (float)nmv;
            float nnm = (float)(NCELL - nzv);
            const float inv = 1.0f / (float)NCELL;
            float lx = ((float)a0 * inv) / nm;
            float ly = ((float)a1v * inv) / nm;
            float lw = ((float)a2v * inv) / nm;
            float lh = ((float)a3 * inv) / nm;
            float lconf = ((float)a4 * inv) / nm
                        + 0.5f * ((float)(a5 - a6) * inv) / nnm;
            float lcls = ((float)a7 / (nm * (float)Cn)) / nm;
            float loss = 2.5f * (lx + ly) + 2.5f * (lw + lh) + lconf + lcls;
            out[0] = loss; out[1] = lx; out[2] = ly; out[3] = lw;
            out[4] = lh;   out[5] = lconf; out[6] = lcls;

            // reset cross-launch state for next graph replay
#pragma unroll
            for (int i = 0; i < 8; i++) g_acc[i] = 0.0;
            g_nm_tot = 0; g_nz_tot = 0;
            __threadfence();
            g_done = 0u;
        }
    }
}

// ---------------- launch ----------------
extern "C" void kernel_launch(void* const* d_in, const int* in_sizes, int n_in,
                              void* d_out, int out_size)
{
    const float* in  = (const float*)d_in[0];   // (16, 255, 76, 76) fp32
    const float* tgt = (const float*)d_in[1];   // (16, 50, 5) fp32
    float* out = (float*)d_out;                 // 7 fp32 scalars

    yolo_one<<<NBLK, NTHR>>>(in, tgt, out);
}

// round 12
// speedup vs baseline: 1.7069x; 1.7069x over previous
#include <cuda_runtime.h>

// ---------------- problem constants ----------------
#define Bn 16
#define An 3
#define Cn 80
#define Hn 76
#define Wn 76
#define Tn 50
#define HW (Hn * Wn)          // 5776
#define AHW (An * HW)         // 17328
#define NCELL (Bn * AHW)      // 277248
#define NT (Bn * Tn)          // 800
#define CH (5 + Cn)           // 85
#define NCH (An * CH)         // 255
#define NREP 8
#define NBB (Bn * NREP)       // 128 batch-replica blocks
#define NTHR 128
#define NBLK 592              // 4 blocks/SM on 148 SMs
#define NWARP (NTHR / 32)
#define ACCPAD 32             // 32 doubles = 256B -> distinct LTS slices

// ---------------- device state (static, zero-init; no allocations) ----------------
__device__ int          g_win[NREP * NCELL];  // per-replica winner tables (self-cleaned)
__device__ double       g_acc[8 * ACCPAD];    // padded accumulators (winner-reset)
__device__ unsigned int g_done;               // ticket (winner-reset)
__device__ int          g_nm_tot, g_nz_tot;   // winner-reset

#define LOG2E 1.4426950408889634f
#define LN2   0.6931471805599453f

// softplus(l) = -log(1-sigmoid(l)) = log(1+e^l); clip(-100) never active for |l| < 17
__device__ __forceinline__ float spf(float l) {
    return LN2 * __log2f(1.0f + exp2f(l * LOG2E));
}
// sum of 4 softplus via one log of product (5 MUFU / 4 terms); product < 3e8 for |l|<6
__device__ __forceinline__ float sp4(float a, float b, float c, float d) {
    float p = (1.0f + exp2f(a * LOG2E)) * (1.0f + exp2f(b * LOG2E))
            * (1.0f + exp2f(c * LOG2E)) * (1.0f + exp2f(d * LOG2E));
    return LN2 * __log2f(p);
}

__global__ __launch_bounds__(NTHR)
void yolo_one(const float* __restrict__ in, const float* __restrict__ tgt,
              float* __restrict__ out)
{
    __shared__ int    s_mcell[16];     // ≤7 winners per replica
    __shared__ float4 s_mt[16];
    __shared__ int    s_pl[16];        // ≤7 pairs per replica
    __shared__ int    s_zc[32];        // ≤21 z-cells per replica
    __shared__ int    s_nm, s_np, s_nz;
    __shared__ float  s_part[NWARP][8];

    const int tid = threadIdx.x, bid = blockIdx.x;
    float f[8];
#pragma unroll
    for (int i = 0; i < 8; i++) f[i] = 0.0f;

    // ================= batch-replica blocks: target build + gather terms =========
    if (bid < NBB) {
        const int b = bid & (Bn - 1);          // batch
        const int r = bid >> 4;                // replica 0..7
        if (tid == 0) { s_nm = 0; s_np = 0; s_nz = 0; }
        __syncthreads();

        const int t = tid;                     // target index within batch
        const bool active = (t < Tn);
        const int j = b * Tn + t;

        // ---- R9-VERBATIM per-target math ----
        float c = 0.f, xx = 0.f, yy = 0.f, ww = 0.f, hh = 0.f;
        if (active) {
            const float* p = tgt + j * 5;
            c = p[0]; xx = p[1]; yy = p[2]; ww = p[3]; hh = p[4];
        }
        bool valid = active && ((c + xx + yy + ww + hh) != 0.0f);

        float gx = xx * (float)Wn, gy = yy * (float)Hn;
        float gw = ww * (float)Wn, gh = hh * (float)Hn;
        int gi = (int)gx, gj = (int)gy;

        const float aw0 = 1.25f,  aw1 = 2.0f,  aw2 = 4.125f;
        const float ah0 = 1.625f, ah1 = 3.75f, ah2 = 2.875f;
        const float a20 = 5.90625f, a21 = 14.25f, a22 = 19.859375f;

        float a1 = (gw + 1.0f) * (gh + 1.0f);
        float i0 = fmaxf(fminf(gw, aw0) + 1.0f, 0.0f) * fmaxf(fminf(gh, ah0) + 1.0f, 0.0f);
        float i1 = fmaxf(fminf(gw, aw1) + 1.0f, 0.0f) * fmaxf(fminf(gh, ah1) + 1.0f, 0.0f);
        float i2 = fmaxf(fminf(gw, aw2) + 1.0f, 0.0f) * fmaxf(fminf(gh, ah2) + 1.0f, 0.0f);
        float u0 = i0 / (a1 + a20 - i0 + 1e-16f);
        float u1 = i1 / (a1 + a21 - i1 + 1e-16f);
        float u2 = i2 / (a1 + a22 - i2 + 1e-16f);

        int best = 0; float bi = u0;
        if (u1 > bi) { best = 1; bi = u1; }
        if (u2 > bi) { best = 2; bi = u2; }

        bool ok = valid && (gj < Hn) && (gi < Wn) && (gj >= 0) && (gi >= 0);
        int cell = ((b * An + best) * Hn + gj) * Wn + gi;

        const bool mine = ((t & (NREP - 1)) == r);   // deterministic partition by t
        int* win = g_win + r * NCELL;                // replica-private table

        // clear-then-max election, bit-identical to R9/R10
        if (ok) win[cell] = 0;
        __syncthreads();
        if (ok) atomicMax(&win[cell], t + 1);

        if (valid && mine) {
            if (u0 > 0.5f) { int z = ((b * An + 0) * Hn + gj) * Wn + gi;
                             if (z >= 0 && z < NCELL) s_zc[atomicAdd(&s_nz, 1)] = z; }
            if (u1 > 0.5f) { int z = ((b * An + 1) * Hn + gj) * Wn + gi;
                             if (z >= 0 && z < NCELL) s_zc[atomicAdd(&s_nz, 1)] = z; }
            if (u2 > 0.5f) { int z = ((b * An + 2) * Hn + gj) * Wn + gi;
                             if (z >= 0 && z < NCELL) s_zc[atomicAdd(&s_nz, 1)] = z; }
        }
        if (ok && mine) s_pl[atomicAdd(&s_np, 1)] = cell * Cn + (int)c;

        __syncthreads();

        if (ok && mine && win[cell] == t + 1) {
            float tx = gx - (float)gi;
            float ty = gy - (float)gj;
            float awb = (best == 0) ? aw0 : (best == 1 ? aw1 : aw2);
            float ahb = (best == 0) ? ah0 : (best == 1 ? ah1 : ah2);
            float tw = logf(gw / awb + 1e-16f);
            float th = logf(gh / ahb + 1e-16f);
            int m = atomicAdd(&s_nm, 1);
            s_mcell[m] = cell;
            s_mt[m] = make_float4(tx, ty, tw, th);
        }
        __syncthreads();

        if (tid == 0) { atomicAdd(&g_nm_tot, s_nm); atomicAdd(&g_nz_tot, s_nz); }

        // ---- block-local gather segments (fp32 per-thread accumulate) ----
        const int nmL = s_nm, npL = s_np, nzL = s_nz;
        const int G1 = nmL;                 // masked x/y/w/h/conf
        const int G2 = G1 + nmL * 20;       // class terms, groups of 4
        const int G3 = G2 + npL;            // pair corrections (exact -logit)
        const int G4 = G3 + nzL;            // noobj-zeroed conf terms

        for (int i = tid; i < G4; i += NTHR) {
            if (i < G1) {
                int cell2 = s_mcell[i]; float4 tv = s_mt[i];
                int bb = cell2 / AHW, rr = cell2 - bb * AHW;
                int a = rr / HW,     hw = rr - a * HW;
                const float* base = in + (size_t)(bb * NCH + a * CH) * HW + hw;
                float xl = base[0], yl = base[HW], wl = base[2 * HW];
                float hl = base[3 * HW], cl = base[4 * HW];
                f[0] += tv.x * spf(-xl) + (1.0f - tv.x) * spf(xl);
                f[1] += tv.y * spf(-yl) + (1.0f - tv.y) * spf(yl);
                float dw = wl - tv.z, dh = hl - tv.w;
                f[2] += dw * dw;
                f[3] += dh * dh;
                f[4] += spf(-cl);
            } else if (i < G2) {
                int idx = i - G1;
                int k = idx / 20, g = idx - k * 20;
                int cell2 = s_mcell[k];
                int bb = cell2 / AHW, rr = cell2 - bb * AHW;
                int a = rr / HW,     hw = rr - a * HW;
                const float* base = in + (size_t)(bb * NCH + a * CH + 5 + g * 4) * HW + hw;
                f[7] += sp4(base[0], base[HW], base[2 * HW], base[3 * HW]);
            } else if (i < G3) {
                int key = s_pl[i - G2];
                int cell2 = key / Cn, cc = key - cell2 * Cn;
                int bb = cell2 / AHW, rr = cell2 - bb * AHW;
                int a = rr / HW,     hw = rr - a * HW;
                f[7] -= in[(size_t)(bb * NCH + a * CH + 5 + cc) * HW + hw];
            } else {
                int cell2 = s_zc[i - G3];
                int bb = cell2 / AHW, rr = cell2 - bb * AHW;
                int a = rr / HW,     hw = rr - a * HW;
                f[6] += spf(in[(size_t)(bb * NCH + a * CH + 4) * HW + hw]);
            }
        }
    }

    // ================= conf segment over all cells (all blocks) ==================
    const int N4 = NCELL / 4;
    for (int i = bid * NTHR + tid; i < N4; i += NBLK * NTHR) {
        int c4 = i * 4;
        int bb = c4 / AHW, rr = c4 - bb * AHW;
        int a = rr / HW,   hw = rr - a * HW;
        const float4 v = *(const float4*)(in + (size_t)(bb * NCH + a * CH + 4) * HW + hw);
        f[5] += sp4(v.x, v.y, v.z, v.w);
    }

    // ================= reduction: fp32 warp -> smem -> fp64 tid0 =================
#pragma unroll
    for (int off = 16; off; off >>= 1)
        f[5] += __shfl_down_sync(0xffffffffu, f[5], off);
    if (bid < NBB) {
#pragma unroll
        for (int off = 16; off; off >>= 1) {
            f[0] += __shfl_down_sync(0xffffffffu, f[0], off);
            f[1] += __shfl_down_sync(0xffffffffu, f[1], off);
            f[2] += __shfl_down_sync(0xffffffffu, f[2], off);
            f[3] += __shfl_down_sync(0xffffffffu, f[3], off);
            f[4] += __shfl_down_sync(0xffffffffu, f[4], off);
            f[6] += __shfl_down_sync(0xffffffffu, f[6], off);
            f[7] += __shfl_down_sync(0xffffffffu, f[7], off);
        }
    }
    int warp = tid >> 5, lane = tid & 31;
    if (lane == 0)
#pragma unroll
        for (int i = 0; i < 8; i++) s_part[warp][i] = f[i];
    __syncthreads();

    if (tid == 0) {
        // fp64 from warp level up; 8 REDs to 8 distinct LTS slices (padded)
#pragma unroll
        for (int i = 0; i < 8; i++) {
            double s = 0.0;
            for (int w = 0; w < NWARP; w++) s += (double)s_part[w][i];
            atomicAdd(&g_acc[i * ACCPAD], s);
        }
        __threadfence();                       // same-thread: REDs before ticket
        unsigned n = atomicAdd(&g_done, 1u);
        if (n == (unsigned)(NBLK - 1)) {
            // ---- winner: finalize (reads via L2 atomics) + reset ----
            double a0 = atomicAdd(&g_acc[0 * ACCPAD], 0.0);
            double a1v = atomicAdd(&g_acc[1 * ACCPAD], 0.0);
            double a2v = atomicAdd(&g_acc[2 * ACCPAD], 0.0);
            double a3 = atomicAdd(&g_acc[3 * ACCPAD], 0.0);
            double a4 = atomicAdd(&g_acc[4 * ACCPAD], 0.0);
            double a5 = atomicAdd(&g_acc[5 * ACCPAD], 0.0);
            double a6 = atomicAdd(&g_acc[6 * ACCPAD], 0.0);
            double a7 = atomicAdd(&g_acc[7 * ACCPAD], 0.0);
            int nmv = atomicAdd(&g_nm_tot, 0), nzv = atomicAdd(&g_nz_tot, 0);

            float nm  = (float)nmv;
            float nnm = (float)(NCELL - nzv);
            const float inv = 1.0f / (float)NCELL;
            float lx = ((float)a0 * inv) / nm;
            float ly = ((float)a1v * inv) / nm;
            float lw = ((float)a2v * inv) / nm;
            float lh = ((float)a3 * inv) / nm;
            float lconf = ((float)a4 * inv) / nm
                        + 0.5f * ((float)(a5 - a6) * inv) / nnm;
            float lcls = ((float)a7 / (nm * (float)Cn)) / nm;
            float loss = 2.5f * (lx + ly) + 2.5f * (lw + lh) + lconf + lcls;
            out[0] = loss; out[1] = lx; out[2] = ly; out[3] = lw;
            out[4] = lh;   out[5] = lconf; out[6] = lcls;

            // reset cross-launch state for next graph replay
#pragma unroll
            for (int i = 0; i < 8; i++) g_acc[i * ACCPAD] = 0.0;
            g_nm_tot = 0; g_nz_tot = 0;
            __threadfence();
            g_done = 0u;
        }
    }
}

// ---------------- launch ----------------
extern "C" void kernel_launch(void* const* d_in, const int* in_sizes, int n_in,
                              void* d_out, int out_size)
{
    const float* in  = (const float*)d_in[0];   // (16, 255, 76, 76) fp32
    const float* tgt = (const float*)d_in[1];   // (16, 50, 5) fp32
    float* out = (float*)d_out;                 // 7 fp32 scalars

    yolo_one<<<NBLK, NTHR>>>(in, tgt, out);
}